// round 1
// baseline (speedup 1.0000x reference)
#include <cuda_runtime.h>
#include <math.h>

#define N_B   4
#define NP    1024
#define D     256
#define HH    64
#define WW    64
#define HW    4096
#define HEADS 8
#define DH    32

// Scratch (device globals: no allocation allowed in kernel_launch)
__device__ float d_lf_pe[N_B * NP * D];   //  4 MB
__device__ float d_gf_pe[N_B * HW * D];   // 16 MB
__device__ float d_Q[N_B * NP * D];       //  4 MB
__device__ float d_K[N_B * HW * D];       // 16 MB
__device__ float d_V[N_B * HW * D];       // 16 MB
__device__ float d_AO[N_B * NP * D];      //  4 MB

// pos-enc value for flattened position p, feature dim dd, on a g x g grid
// (g = grid width; linspace(0,1,g) -> step 1/(g-1))
__device__ __forceinline__ float pe_val(int p, int dd, int g) {
    int i = dd >> 1;
    float div = expf((float)(2 * i) * (-9.210340371976184f / 256.0f)); // 10000^(-2i/256)
    float coord = (dd & 1) ? (float)(p / g) : (float)(p % g);
    coord *= 1.0f / (float)(g - 1);
    float a = coord * div;
    return (dd & 1) ? cosf(a) : sinf(a);
}

// lf_pe[n,p,d] = local_feat[n,p,d] + pe(p,d) on 32x32 grid
__global__ void add_pe_local(const float* __restrict__ lf) {
    int idx = blockIdx.x * blockDim.x + threadIdx.x;
    if (idx >= N_B * NP * D) return;
    int dd = idx & (D - 1);
    int p  = (idx / D) & (NP - 1);
    d_lf_pe[idx] = lf[idx] + pe_val(p, dd, 32);
}

// gf_pe[n,p,d] = global_feat[n,d,p] + pe(p,d) on 64x64 grid  (transpose via smem)
__global__ void add_pe_global(const float* __restrict__ gf) {
    __shared__ float tile[32][33];
    int p0 = blockIdx.x * 32;
    int d0 = blockIdx.y * 32;
    int n  = blockIdx.z;
    int tx = threadIdx.x;  // 0..31
    int ty = threadIdx.y;  // 0..7
#pragma unroll
    for (int i = 0; i < 4; i++) {
        int dd = d0 + ty + i * 8;
        tile[ty + i * 8][tx] = gf[((size_t)n * D + dd) * HW + p0 + tx];
    }
    __syncthreads();
#pragma unroll
    for (int i = 0; i < 4; i++) {
        int p  = p0 + ty + i * 8;
        int dd = d0 + tx;
        d_gf_pe[((size_t)n * HW + p) * D + dd] = tile[tx][ty + i * 8] + pe_val(p, dd, 64);
    }
}

// C[r, j] = sum_k (A[r,k] (+ A2[r,k])) * W[j,k] + b[j]
// A: R x 256 row-major, W: 256 x 256 row-major (out-dim major), C: R x 256
// grid: (256/32, R/32), block (32, 8). Each thread computes 4 rows x 1 col.
__global__ void gemm_bias(const float* __restrict__ A, const float* __restrict__ A2,
                          const float* __restrict__ W, const float* __restrict__ b,
                          float* __restrict__ C) {
    __shared__ float As[32][33];
    __shared__ float Ws[32][33];
    int tx = threadIdx.x, ty = threadIdx.y;
    int col0 = blockIdx.x * 32;
    int row0 = blockIdx.y * 32;
    float acc[4] = {0.f, 0.f, 0.f, 0.f};

    for (int k0 = 0; k0 < 256; k0 += 32) {
#pragma unroll
        for (int i = 0; i < 4; i++) {
            int r = row0 + ty * 4 + i;
            float v = A[(size_t)r * 256 + k0 + tx];
            if (A2) v += A2[(size_t)r * 256 + k0 + tx];
            As[ty * 4 + i][tx] = v;
            Ws[ty * 4 + i][tx] = W[(size_t)(col0 + ty * 4 + i) * 256 + k0 + tx];
        }
        __syncthreads();
#pragma unroll
        for (int k = 0; k < 32; k++) {
            float wv = Ws[tx][k];
#pragma unroll
            for (int i = 0; i < 4; i++) acc[i] += As[ty * 4 + i][k] * wv;
        }
        __syncthreads();
    }
    float bias = b[col0 + tx];
#pragma unroll
    for (int i = 0; i < 4; i++)
        C[(size_t)(row0 + ty * 4 + i) * 256 + col0 + tx] = acc[i] + bias;
}

// Flash-attention: 1 thread = 1 query. grid (NP/128, HEADS, N_B), block 128.
__global__ void attn_kernel() {
    int qt = blockIdx.x, h = blockIdx.y, n = blockIdx.z;
    int tid = threadIdx.x;
    int q = qt * 128 + tid;

    const float* Qp = d_Q + ((size_t)(n * NP + q)) * D + h * DH;
    float qr[32];
#pragma unroll
    for (int i = 0; i < 32; i++) qr[i] = Qp[i] * 0.17677669529663687f; // 1/sqrt(32)

    float o[32];
#pragma unroll
    for (int i = 0; i < 32; i++) o[i] = 0.f;
    float m = -1e30f, l = 0.f;

    __shared__ float Ks[64][32];
    __shared__ float Vs[64][32];
    const float* Kb = d_K + (size_t)n * HW * D + h * DH;
    const float* Vb = d_V + (size_t)n * HW * D + h * DH;

    for (int k0 = 0; k0 < HW; k0 += 64) {
        __syncthreads();
        // 64 rows x 8 float4 = 512 float4 loads each for K and V, 128 threads
        for (int i = tid; i < 512; i += 128) {
            int r = i >> 3, c = i & 7;
            ((float4*)Ks[r])[c] = *(const float4*)(Kb + (size_t)(k0 + r) * D + c * 4);
            ((float4*)Vs[r])[c] = *(const float4*)(Vb + (size_t)(k0 + r) * D + c * 4);
        }
        __syncthreads();

        float s[64];
#pragma unroll
        for (int k = 0; k < 64; k++) {
            float acc = 0.f;
            const float4* kr = (const float4*)Ks[k];
#pragma unroll
            for (int c = 0; c < 8; c++) {
                float4 kv = kr[c];
                acc += qr[c * 4 + 0] * kv.x;
                acc += qr[c * 4 + 1] * kv.y;
                acc += qr[c * 4 + 2] * kv.z;
                acc += qr[c * 4 + 3] * kv.w;
            }
            s[k] = acc;
        }
        float mt = m;
#pragma unroll
        for (int k = 0; k < 64; k++) mt = fmaxf(mt, s[k]);
        float scale = __expf(m - mt);
        m = mt;
        l *= scale;
#pragma unroll
        for (int i = 0; i < 32; i++) o[i] *= scale;
#pragma unroll
        for (int k = 0; k < 64; k++) {
            float p = __expf(s[k] - m);
            l += p;
            const float4* vr = (const float4*)Vs[k];
#pragma unroll
            for (int c = 0; c < 8; c++) {
                float4 vv = vr[c];
                o[c * 4 + 0] += p * vv.x;
                o[c * 4 + 1] += p * vv.y;
                o[c * 4 + 2] += p * vv.z;
                o[c * 4 + 3] += p * vv.w;
            }
        }
    }
    float inv = 1.f / l;
    float* Op = d_AO + ((size_t)(n * NP + q)) * D + h * DH;
#pragma unroll
    for (int i = 0; i < 32; i++) Op[i] = o[i] * inv;
}

extern "C" void kernel_launch(void* const* d_in, const int* in_sizes, int n_in,
                              void* d_out, int out_size) {
    const float* lf = (const float*)d_in[0];
    const float* gf = (const float*)d_in[1];
    const float* Wq = (const float*)d_in[2];
    const float* bq = (const float*)d_in[3];
    const float* Wk = (const float*)d_in[4];
    const float* bk = (const float*)d_in[5];
    const float* Wv = (const float*)d_in[6];
    const float* bv = (const float*)d_in[7];
    const float* Wo = (const float*)d_in[8];
    const float* bo = (const float*)d_in[9];
    float* out = (float*)d_out;

    float *lf_pe, *gf_pe, *Q, *K, *V, *AO;
    cudaGetSymbolAddress((void**)&lf_pe, d_lf_pe);
    cudaGetSymbolAddress((void**)&gf_pe, d_gf_pe);
    cudaGetSymbolAddress((void**)&Q, d_Q);
    cudaGetSymbolAddress((void**)&K, d_K);
    cudaGetSymbolAddress((void**)&V, d_V);
    cudaGetSymbolAddress((void**)&AO, d_AO);

    // 1. positional encodings
    add_pe_local<<<(N_B * NP * D) / 256, 256>>>(lf);
    add_pe_global<<<dim3(HW / 32, D / 32, N_B), dim3(32, 8)>>>(gf);

    // 2. projections
    gemm_bias<<<dim3(8, (N_B * NP) / 32), dim3(32, 8)>>>(lf_pe, nullptr, Wq, bq, Q);
    gemm_bias<<<dim3(8, (N_B * HW) / 32), dim3(32, 8)>>>(gf_pe, nullptr, Wk, bk, K);
    gemm_bias<<<dim3(8, (N_B * HW) / 32), dim3(32, 8)>>>(gf_pe, nullptr, Wv, bv, V);

    // 3. attention
    attn_kernel<<<dim3(NP / 128, HEADS, N_B), 128>>>();

    // 4. output projection with residual (lf_pe + attn_out) @ Wo^T + bo
    gemm_bias<<<dim3(8, (N_B * NP) / 32), dim3(32, 8)>>>(lf_pe, AO, Wo, bo, out);
}

// round 5
// speedup vs baseline: 2.4977x; 2.4977x over previous
#include <cuda_runtime.h>
#include <math.h>
#include <stdint.h>

#define N_B   4
#define NP    1024
#define D     256
#define HW    4096
#define HEADS 8
#define DH    32

// Scratch (device globals: no allocation allowed in kernel_launch)
__device__ float d_lf_pe[N_B * NP * D];   //  4 MB
__device__ float d_gf_pe[N_B * HW * D];   // 16 MB
__device__ float d_Q[N_B * NP * D];       //  4 MB
__device__ float d_K[N_B * HW * D];       // 16 MB
__device__ float d_V[N_B * HW * D];       // 16 MB
__device__ float d_AO[N_B * NP * D];      //  4 MB

// tcgen05 only legal when compiling an arch-specific ('a') target.
#if defined(__CUDA_ARCH_FEAT_SM103_ALL) || defined(__CUDA_ARCH_FEAT_SM100_ALL) || defined(__CUDA_ARCH_FEAT_SM101_ALL)
#define HAS_TCGEN05 1
#else
#define HAS_TCGEN05 0
#endif

// ---------------------------------------------------------------------------
// Positional encodings
// ---------------------------------------------------------------------------
__device__ __forceinline__ float pe_val(int p, int dd, int g) {
    int i = dd >> 1;
    float div = expf((float)(2 * i) * (-9.210340371976184f / 256.0f));
    float coord = (dd & 1) ? (float)(p / g) : (float)(p % g);
    coord *= 1.0f / (float)(g - 1);
    float a = coord * div;
    return (dd & 1) ? cosf(a) : sinf(a);
}

__global__ void add_pe_local(const float* __restrict__ lf) {
    int idx = blockIdx.x * blockDim.x + threadIdx.x;
    if (idx >= N_B * NP * D) return;
    int dd = idx & (D - 1);
    int p  = (idx / D) & (NP - 1);
    d_lf_pe[idx] = lf[idx] + pe_val(p, dd, 32);
}

__global__ void add_pe_global(const float* __restrict__ gf) {
    __shared__ float tile[32][33];
    int p0 = blockIdx.x * 32, d0 = blockIdx.y * 32, n = blockIdx.z;
    int tx = threadIdx.x, ty = threadIdx.y;
#pragma unroll
    for (int i = 0; i < 4; i++) {
        int dd = d0 + ty + i * 8;
        tile[ty + i * 8][tx] = gf[((size_t)n * D + dd) * HW + p0 + tx];
    }
    __syncthreads();
#pragma unroll
    for (int i = 0; i < 4; i++) {
        int p  = p0 + ty + i * 8;
        int dd = d0 + tx;
        d_gf_pe[((size_t)n * HW + p) * D + dd] = tile[tx][ty + i * 8] + pe_val(p, dd, 64);
    }
}

// ---------------------------------------------------------------------------
// SIMT projection GEMM
// ---------------------------------------------------------------------------
__global__ void gemm_bias(const float* __restrict__ A, const float* __restrict__ A2,
                          const float* __restrict__ W, const float* __restrict__ b,
                          float* __restrict__ C) {
    __shared__ float As[32][33];
    __shared__ float Ws[32][33];
    int tx = threadIdx.x, ty = threadIdx.y;
    int col0 = blockIdx.x * 32, row0 = blockIdx.y * 32;
    float acc[4] = {0.f, 0.f, 0.f, 0.f};

    for (int k0 = 0; k0 < 256; k0 += 32) {
#pragma unroll
        for (int i = 0; i < 4; i++) {
            int r = row0 + ty * 4 + i;
            float v = A[(size_t)r * 256 + k0 + tx];
            if (A2) v += A2[(size_t)r * 256 + k0 + tx];
            As[ty * 4 + i][tx] = v;
            Ws[ty * 4 + i][tx] = W[(size_t)(col0 + ty * 4 + i) * 256 + k0 + tx];
        }
        __syncthreads();
#pragma unroll
        for (int k = 0; k < 32; k++) {
            float wv = Ws[tx][k];
#pragma unroll
            for (int i = 0; i < 4; i++) acc[i] += As[ty * 4 + i][k] * wv;
        }
        __syncthreads();
    }
    float bias = b[col0 + tx];
#pragma unroll
    for (int i = 0; i < 4; i++)
        C[(size_t)(row0 + ty * 4 + i) * 256 + col0 + tx] = acc[i] + bias;
}

// ---------------------------------------------------------------------------
// PTX helpers (guarded)
// ---------------------------------------------------------------------------
#if HAS_TCGEN05
__device__ __forceinline__ uint32_t smem_u32(const void* p) {
    uint32_t a;
    asm("{ .reg .u64 t; cvta.to.shared.u64 t, %1; cvt.u32.u64 %0, t; }" : "=r"(a) : "l"(p));
    return a;
}
__device__ __forceinline__ uint32_t elect_one() {
    uint32_t p;
    asm volatile("{\n\t.reg .pred p;\n\telect.sync _|p, 0xFFFFFFFF;\n\tselp.b32 %0, 1, 0, p;\n\t}" : "=r"(p));
    return p;
}

#define TCG_ALLOC(sm, n)  asm volatile("tcgen05.alloc.cta_group::1.sync.aligned.shared::cta.b32 [%0], %1;" :: "r"(sm), "r"(n) : "memory")
#define TCG_DEALLOC(t, n) asm volatile("tcgen05.dealloc.cta_group::1.sync.aligned.b32 %0, %1;" :: "r"(t), "r"(n))
#define TCG_RELINQ()      asm volatile("tcgen05.relinquish_alloc_permit.cta_group::1.sync.aligned;")
#define TCG_COMMIT(mbar)  asm volatile("tcgen05.commit.cta_group::1.mbarrier::arrive::one.shared::cluster.b64 [%0];" :: "r"(mbar) : "memory")
#define TCG_WAIT_LD()     asm volatile("tcgen05.wait::ld.sync.aligned;" ::: "memory")
#define TCG_WAIT_ST()     asm volatile("tcgen05.wait::st.sync.aligned;" ::: "memory")
#define TCG_FENCE_BEFORE() asm volatile("tcgen05.fence::before_thread_sync;" ::: "memory")
#define TCG_FENCE_AFTER()  asm volatile("tcgen05.fence::after_thread_sync;" ::: "memory")
#define FENCE_ASYNC_SHARED() asm volatile("fence.proxy.async.shared::cta;" ::: "memory")
#define MBAR_INIT(m, c)   asm volatile("mbarrier.init.shared.b64 [%0], %1;" :: "r"(m), "r"(c) : "memory")

__device__ __forceinline__ void mbar_wait(uint32_t mbar, uint32_t parity) {
    asm volatile(
        "{\n\t.reg .pred P;\n\t"
        "W_%=:\n\t"
        "mbarrier.try_wait.parity.acquire.cta.shared::cta.b64 P, [%0], %1, 0x989680;\n\t"
        "@!P bra W_%=;\n\t}"
        :: "r"(mbar), "r"(parity) : "memory");
}

__device__ __forceinline__ void mma_tf32_ts(uint32_t d_tmem, uint32_t a_tmem,
                                            uint64_t b_desc, uint32_t idesc, bool acc) {
    uint32_t en = acc ? 1u : 0u;
    uint32_t z = 0;
    asm volatile(
        "{\n\t.reg .pred p;\n\t"
        "setp.ne.u32 p, %5, 0;\n\t"
        "tcgen05.mma.cta_group::1.kind::tf32 [%0], [%1], %2, %3, {%4, %4, %4, %4}, p;\n\t}"
        :: "r"(d_tmem), "r"(a_tmem), "l"(b_desc), "r"(idesc), "r"(z), "r"(en)
        : "memory");
}

#define TCG_LD_X32(r, addr) \
    asm volatile("tcgen05.ld.sync.aligned.32x32b.x32.b32 " \
        "{%0,%1,%2,%3,%4,%5,%6,%7,%8,%9,%10,%11,%12,%13,%14,%15," \
        "%16,%17,%18,%19,%20,%21,%22,%23,%24,%25,%26,%27,%28,%29,%30,%31}, [%32];" \
        : "=r"((r)[0]),"=r"((r)[1]),"=r"((r)[2]),"=r"((r)[3]),"=r"((r)[4]),"=r"((r)[5]),"=r"((r)[6]),"=r"((r)[7]), \
          "=r"((r)[8]),"=r"((r)[9]),"=r"((r)[10]),"=r"((r)[11]),"=r"((r)[12]),"=r"((r)[13]),"=r"((r)[14]),"=r"((r)[15]), \
          "=r"((r)[16]),"=r"((r)[17]),"=r"((r)[18]),"=r"((r)[19]),"=r"((r)[20]),"=r"((r)[21]),"=r"((r)[22]),"=r"((r)[23]), \
          "=r"((r)[24]),"=r"((r)[25]),"=r"((r)[26]),"=r"((r)[27]),"=r"((r)[28]),"=r"((r)[29]),"=r"((r)[30]),"=r"((r)[31]) \
        : "r"(addr))

#define TCG_ST_X32(addr, r) \
    asm volatile("tcgen05.st.sync.aligned.32x32b.x32.b32 [%0], " \
        "{%1,%2,%3,%4,%5,%6,%7,%8,%9,%10,%11,%12,%13,%14,%15,%16," \
        "%17,%18,%19,%20,%21,%22,%23,%24,%25,%26,%27,%28,%29,%30,%31,%32};" \
        :: "r"(addr), \
           "r"((r)[0]),"r"((r)[1]),"r"((r)[2]),"r"((r)[3]),"r"((r)[4]),"r"((r)[5]),"r"((r)[6]),"r"((r)[7]), \
           "r"((r)[8]),"r"((r)[9]),"r"((r)[10]),"r"((r)[11]),"r"((r)[12]),"r"((r)[13]),"r"((r)[14]),"r"((r)[15]), \
           "r"((r)[16]),"r"((r)[17]),"r"((r)[18]),"r"((r)[19]),"r"((r)[20]),"r"((r)[21]),"r"((r)[22]),"r"((r)[23]), \
           "r"((r)[24]),"r"((r)[25]),"r"((r)[26]),"r"((r)[27]),"r"((r)[28]),"r"((r)[29]),"r"((r)[30]),"r"((r)[31]) \
        : "memory")

static __device__ __forceinline__ uint64_t make_desc_sw128(uint32_t base) {
    const uint64_t BASE =
        (uint64_t(2)  << 61) | (uint64_t(1) << 46) | (uint64_t(64) << 32) | (uint64_t(1) << 16);
    return BASE | ((uint64_t)(base >> 4) & 0x3FFF);
}
__device__ __forceinline__ uint32_t sw128(uint32_t b) { return b ^ ((b >> 3) & 0x70); }

// idesc: dtype=F32(1<<4) | atype=TF32(2<<7) | btype=TF32(2<<10) | (N/8)<<17 | (M/16)<<24
#define IDESC_S 0x8200910u  /* M=128, N=128 */
#define IDESC_O 0x8080910u  /* M=128, N=32  */
#endif // HAS_TCGEN05

// ---------------------------------------------------------------------------
// Attention kernel: tcgen05 tf32 path if available, SIMT flash fallback else.
//   grid (NP/128, HEADS, N_B), block 128, dynamic smem ATTN_SMEM
// ---------------------------------------------------------------------------
#define SMEM_K_OFF 1024
#define SMEM_V_OFF (1024 + 16384)
#define ATTN_SMEM  (1024 + 32768)
#define TM_Q 0
#define TM_O 32
#define TM_S 128
#define TM_COLS 256

__global__ void __launch_bounds__(128, 2)
attn_tc_kernel() {
    extern __shared__ char smem[];
    int tid = threadIdx.x;
    int qt = blockIdx.x, h = blockIdx.y, n = blockIdx.z;

#if HAS_TCGEN05
    uint32_t sb = smem_u32(smem);
    int wid = tid >> 5;

    if (wid == 0) TCG_ALLOC(sb, TM_COLS);
    if (tid == 0) { MBAR_INIT(sb + 8, 1); MBAR_INIT(sb + 16, 1); }
    __syncthreads();
    uint32_t tb;
    asm volatile("ld.shared.b32 %0, [%1];" : "=r"(tb) : "r"(sb));
    if (wid == 0) TCG_RELINQ();

    uint32_t woff = (uint32_t)wid << 21;

    // Stage Q (pre-scaled by 1/sqrt(DH)) into TMEM: row = tid, 32 tf32 cols
    {
        const float* Qp = d_Q + ((size_t)(n * NP + qt * 128 + tid)) * D + h * DH;
        uint32_t qr[32];
#pragma unroll
        for (int i = 0; i < 32; i++)
            qr[i] = __float_as_uint(Qp[i] * 0.17677669529663687f);
        TCG_ST_X32(tb + TM_Q + woff, qr);
        TCG_WAIT_ST();
    }
    TCG_FENCE_BEFORE();
    __syncthreads();

    const float* Kb = d_K + (size_t)n * HW * D + h * DH;
    const float* Vb = d_V + (size_t)n * HW * D + h * DH;
    uint64_t kdesc = make_desc_sw128(sb + SMEM_K_OFF);
    uint64_t vdesc = make_desc_sw128(sb + SMEM_V_OFF);
    float l = 0.f;

    for (int t = 0; t < 32; t++) {
        uint32_t par = (uint32_t)(t & 1);

        // K tile: SW128 K-major (row=key, 32 tf32 = 128B). V tile: transposed
        // blocked-atom layout (atom 8 dh-rows x 32 keys, atom_off = ar + ac*4).
#pragma unroll
        for (int i = 0; i < 8; i++) {
            int f = i * 128 + tid;
            int k = f >> 3;
            int c = (f & 7) * 4;
            const float4 kv = *(const float4*)(Kb + (size_t)(t * 128 + k) * D + c);
            *(float4*)(smem + SMEM_K_OFF + sw128((uint32_t)(k * 128 + c * 4))) = kv;
            const float4 vv = *(const float4*)(Vb + (size_t)(t * 128 + k) * D + c);
            int ac = k >> 5, ic = k & 31;
#pragma unroll
            for (int j = 0; j < 4; j++) {
                int dh = c + j;
                uint32_t vb = (uint32_t)(((dh >> 3) + ac * 4) * 1024 + (dh & 7) * 128 + ic * 4);
                *(float*)(smem + SMEM_V_OFF + sw128(vb)) = (&vv.x)[j];
            }
        }
        FENCE_ASYNC_SHARED();
        __syncthreads();

        // S = Q @ K^T  (M=128, N=128, K=32 -> 4 tf32 k-steps of K=8)
        if (wid == 0) {
            TCG_FENCE_AFTER();
            if (elect_one()) {
#pragma unroll
                for (int s = 0; s < 4; s++)
                    mma_tf32_ts(tb + TM_S, tb + TM_Q + s * 8, kdesc + s * 2, IDESC_S, s > 0);
                TCG_COMMIT(sb + 8);
            }
        }
        mbar_wait(sb + 8, par);
        TCG_FENCE_AFTER();

        // softmax without max-subtraction (scores bounded ~|10|): P = exp(S)
#pragma unroll
        for (int cc = 0; cc < 4; cc++) {
            uint32_t r[32];
            TCG_LD_X32(r, tb + TM_S + cc * 32);
            TCG_WAIT_LD();
#pragma unroll
            for (int j = 0; j < 32; j++) {
                float p = __expf(__uint_as_float(r[j]));
                l += p;
                r[j] = __float_as_uint(p);
            }
            TCG_ST_X32(tb + TM_S + cc * 32 + woff, r);
        }
        TCG_WAIT_ST();
        TCG_FENCE_BEFORE();
        __syncthreads();

        // O += P @ V  (M=128, N=32, K=128 -> 16 k-steps over V^T atoms)
        if (wid == 0) {
            TCG_FENCE_AFTER();
            if (elect_one()) {
#pragma unroll
                for (int s = 0; s < 16; s++)
                    mma_tf32_ts(tb + TM_O, tb + TM_S + s * 8,
                                vdesc + (uint64_t)((s >> 2) * 256 + (s & 3) * 2),
                                IDESC_O, (t > 0) || (s > 0));
                TCG_COMMIT(sb + 16);
            }
        }
        mbar_wait(sb + 16, par);
    }

    TCG_FENCE_AFTER();
    uint32_t o[32];
    TCG_LD_X32(o, tb + TM_O);
    TCG_WAIT_LD();
    float inv = 1.f / l;
    float* Op = d_AO + ((size_t)(n * NP + qt * 128 + tid)) * D + h * DH;
#pragma unroll
    for (int j = 0; j < 32; j++) Op[j] = __uint_as_float(o[j]) * inv;

    TCG_FENCE_BEFORE();
    __syncthreads();
    if (wid == 0) TCG_DEALLOC(tb, TM_COLS);

#else  // ---------------- SIMT fallback (known-good round-1 path) ----------
    float* Ks = (float*)smem;                 // [64][32]
    float* Vs = (float*)smem + 64 * 32;       // [64][32]
    int q = qt * 128 + tid;

    const float* Qp = d_Q + ((size_t)(n * NP + q)) * D + h * DH;
    float qr[32];
#pragma unroll
    for (int i = 0; i < 32; i++) qr[i] = Qp[i] * 0.17677669529663687f;

    float o[32];
#pragma unroll
    for (int i = 0; i < 32; i++) o[i] = 0.f;
    float m = -1e30f, l = 0.f;

    const float* Kb = d_K + (size_t)n * HW * D + h * DH;
    const float* Vb = d_V + (size_t)n * HW * D + h * DH;

    for (int k0 = 0; k0 < HW; k0 += 64) {
        __syncthreads();
        for (int i = tid; i < 512; i += 128) {
            int r = i >> 3, c = i & 7;
            ((float4*)(Ks + r * 32))[c] = *(const float4*)(Kb + (size_t)(k0 + r) * D + c * 4);
            ((float4*)(Vs + r * 32))[c] = *(const float4*)(Vb + (size_t)(k0 + r) * D + c * 4);
        }
        __syncthreads();

        float s[64];
#pragma unroll
        for (int k = 0; k < 64; k++) {
            float acc = 0.f;
            const float4* kr = (const float4*)(Ks + k * 32);
#pragma unroll
            for (int c = 0; c < 8; c++) {
                float4 kv = kr[c];
                acc += qr[c * 4 + 0] * kv.x;
                acc += qr[c * 4 + 1] * kv.y;
                acc += qr[c * 4 + 2] * kv.z;
                acc += qr[c * 4 + 3] * kv.w;
            }
            s[k] = acc;
        }
        float mt = m;
#pragma unroll
        for (int k = 0; k < 64; k++) mt = fmaxf(mt, s[k]);
        float scale = __expf(m - mt);
        m = mt;
        l *= scale;
#pragma unroll
        for (int i = 0; i < 32; i++) o[i] *= scale;
#pragma unroll
        for (int k = 0; k < 64; k++) {
            float p = __expf(s[k] - m);
            l += p;
            const float4* vr = (const float4*)(Vs + k * 32);
#pragma unroll
            for (int c = 0; c < 8; c++) {
                float4 vv = vr[c];
                o[c * 4 + 0] += p * vv.x;
                o[c * 4 + 1] += p * vv.y;
                o[c * 4 + 2] += p * vv.z;
                o[c * 4 + 3] += p * vv.w;
            }
        }
    }
    float inv = 1.f / l;
    float* Op = d_AO + ((size_t)(n * NP + q)) * D + h * DH;
#pragma unroll
    for (int i = 0; i < 32; i++) Op[i] = o[i] * inv;
#endif
}

// ---------------------------------------------------------------------------
extern "C" void kernel_launch(void* const* d_in, const int* in_sizes, int n_in,
                              void* d_out, int out_size) {
    const float* lf = (const float*)d_in[0];
    const float* gf = (const float*)d_in[1];
    const float* Wq = (const float*)d_in[2];
    const float* bq = (const float*)d_in[3];
    const float* Wk = (const float*)d_in[4];
    const float* bk = (const float*)d_in[5];
    const float* Wv = (const float*)d_in[6];
    const float* bv = (const float*)d_in[7];
    const float* Wo = (const float*)d_in[8];
    const float* bo = (const float*)d_in[9];
    float* out = (float*)d_out;

    float *lf_pe, *gf_pe, *Q, *K, *V, *AO;
    cudaGetSymbolAddress((void**)&lf_pe, d_lf_pe);
    cudaGetSymbolAddress((void**)&gf_pe, d_gf_pe);
    cudaGetSymbolAddress((void**)&Q, d_Q);
    cudaGetSymbolAddress((void**)&K, d_K);
    cudaGetSymbolAddress((void**)&V, d_V);
    cudaGetSymbolAddress((void**)&AO, d_AO);

    add_pe_local<<<(N_B * NP * D) / 256, 256>>>(lf);
    add_pe_global<<<dim3(HW / 32, D / 32, N_B), dim3(32, 8)>>>(gf);

    gemm_bias<<<dim3(8, (N_B * NP) / 32), dim3(32, 8)>>>(lf_pe, nullptr, Wq, bq, Q);
    gemm_bias<<<dim3(8, (N_B * HW) / 32), dim3(32, 8)>>>(gf_pe, nullptr, Wk, bk, K);
    gemm_bias<<<dim3(8, (N_B * HW) / 32), dim3(32, 8)>>>(gf_pe, nullptr, Wv, bv, V);

    attn_tc_kernel<<<dim3(NP / 128, HEADS, N_B), 128, ATTN_SMEM>>>();

    gemm_bias<<<dim3(8, (N_B * NP) / 32), dim3(32, 8)>>>(lf_pe, AO, Wo, bo, out);
}

// round 10
// speedup vs baseline: 4.5334x; 1.8150x over previous
#include <cuda_runtime.h>
#include <math.h>
#include <stdint.h>

#define N_B   4
#define NP    1024
#define D     256
#define HW    4096
#define HEADS 8
#define DH    32

// Scratch (device globals: no allocation allowed in kernel_launch)
__device__ float d_lf_pe[N_B * NP * D];   //  4 MB
__device__ float d_gf_pe[N_B * HW * D];   // 16 MB
__device__ float d_Q[N_B * NP * D];       //  4 MB
__device__ float d_K[N_B * HW * D];       // 16 MB
__device__ float d_V[N_B * HW * D];       // 16 MB
__device__ float d_AO[N_B * NP * D];      //  4 MB

// tcgen05 only legal when compiling an arch-specific ('a') target.
#if defined(__CUDA_ARCH_FEAT_SM103_ALL) || defined(__CUDA_ARCH_FEAT_SM100_ALL) || defined(__CUDA_ARCH_FEAT_SM101_ALL)
#define HAS_TCGEN05 1
#else
#define HAS_TCGEN05 0
#endif

// ---------------------------------------------------------------------------
// Positional encodings
// ---------------------------------------------------------------------------
__device__ __forceinline__ float pe_val(int p, int dd, int g) {
    int i = dd >> 1;
    float div = expf((float)(2 * i) * (-9.210340371976184f / 256.0f));
    float coord = (dd & 1) ? (float)(p / g) : (float)(p % g);
    coord *= 1.0f / (float)(g - 1);
    float a = coord * div;
    return (dd & 1) ? cosf(a) : sinf(a);
}

__global__ void add_pe_local(const float* __restrict__ lf) {
    int idx = blockIdx.x * blockDim.x + threadIdx.x;
    if (idx >= N_B * NP * D) return;
    int dd = idx & (D - 1);
    int p  = (idx / D) & (NP - 1);
    d_lf_pe[idx] = lf[idx] + pe_val(p, dd, 32);
}

__global__ void add_pe_global(const float* __restrict__ gf) {
    __shared__ float tile[32][33];
    int p0 = blockIdx.x * 32, d0 = blockIdx.y * 32, n = blockIdx.z;
    int tx = threadIdx.x, ty = threadIdx.y;
#pragma unroll
    for (int i = 0; i < 4; i++) {
        int dd = d0 + ty + i * 8;
        tile[ty + i * 8][tx] = gf[((size_t)n * D + dd) * HW + p0 + tx];
    }
    __syncthreads();
#pragma unroll
    for (int i = 0; i < 4; i++) {
        int p  = p0 + ty + i * 8;
        int dd = d0 + tx;
        d_gf_pe[((size_t)n * HW + p) * D + dd] = tile[tx][ty + i * 8] + pe_val(p, dd, 64);
    }
}

// ---------------------------------------------------------------------------
// PTX helpers (guarded)
// ---------------------------------------------------------------------------
#if HAS_TCGEN05
__device__ __forceinline__ uint32_t smem_u32(const void* p) {
    uint32_t a;
    asm("{ .reg .u64 t; cvta.to.shared.u64 t, %1; cvt.u32.u64 %0, t; }" : "=r"(a) : "l"(p));
    return a;
}
__device__ __forceinline__ uint32_t elect_one() {
    uint32_t p;
    asm volatile("{\n\t.reg .pred p;\n\telect.sync _|p, 0xFFFFFFFF;\n\tselp.b32 %0, 1, 0, p;\n\t}" : "=r"(p));
    return p;
}

#define TCG_ALLOC(sm, n)  asm volatile("tcgen05.alloc.cta_group::1.sync.aligned.shared::cta.b32 [%0], %1;" :: "r"(sm), "r"(n) : "memory")
#define TCG_DEALLOC(t, n) asm volatile("tcgen05.dealloc.cta_group::1.sync.aligned.b32 %0, %1;" :: "r"(t), "r"(n))
#define TCG_RELINQ()      asm volatile("tcgen05.relinquish_alloc_permit.cta_group::1.sync.aligned;")
#define TCG_COMMIT(mbar)  asm volatile("tcgen05.commit.cta_group::1.mbarrier::arrive::one.shared::cluster.b64 [%0];" :: "r"(mbar) : "memory")
#define TCG_WAIT_LD()     asm volatile("tcgen05.wait::ld.sync.aligned;" ::: "memory")
#define TCG_WAIT_ST()     asm volatile("tcgen05.wait::st.sync.aligned;" ::: "memory")
#define TCG_FENCE_BEFORE() asm volatile("tcgen05.fence::before_thread_sync;" ::: "memory")
#define TCG_FENCE_AFTER()  asm volatile("tcgen05.fence::after_thread_sync;" ::: "memory")
#define FENCE_ASYNC_SHARED() asm volatile("fence.proxy.async.shared::cta;" ::: "memory")
#define MBAR_INIT(m, c)   asm volatile("mbarrier.init.shared.b64 [%0], %1;" :: "r"(m), "r"(c) : "memory")

__device__ __forceinline__ void mbar_wait(uint32_t mbar, uint32_t parity) {
    asm volatile(
        "{\n\t.reg .pred P;\n\t"
        "W_%=:\n\t"
        "mbarrier.try_wait.parity.acquire.cta.shared::cta.b64 P, [%0], %1, 0x989680;\n\t"
        "@!P bra W_%=;\n\t}"
        :: "r"(mbar), "r"(parity) : "memory");
}

// tf32 MMA, TS form (A in TMEM)
__device__ __forceinline__ void mma_tf32_ts(uint32_t d_tmem, uint32_t a_tmem,
                                            uint64_t b_desc, uint32_t idesc, bool acc) {
    uint32_t en = acc ? 1u : 0u;
    uint32_t z = 0;
    asm volatile(
        "{\n\t.reg .pred p;\n\t"
        "setp.ne.u32 p, %5, 0;\n\t"
        "tcgen05.mma.cta_group::1.kind::tf32 [%0], [%1], %2, %3, {%4, %4, %4, %4}, p;\n\t}"
        :: "r"(d_tmem), "r"(a_tmem), "l"(b_desc), "r"(idesc), "r"(z), "r"(en)
        : "memory");
}

// tf32 MMA, SS form (A via smem descriptor)
__device__ __forceinline__ void mma_tf32_ss(uint32_t d_tmem, uint64_t a_desc,
                                            uint64_t b_desc, uint32_t idesc, bool acc) {
    uint32_t en = acc ? 1u : 0u;
    uint32_t z = 0;
    asm volatile(
        "{\n\t.reg .pred p;\n\t"
        "setp.ne.u32 p, %5, 0;\n\t"
        "tcgen05.mma.cta_group::1.kind::tf32 [%0], %1, %2, %3, {%4, %4, %4, %4}, p;\n\t}"
        :: "r"(d_tmem), "l"(a_desc), "l"(b_desc), "r"(idesc), "r"(z), "r"(en)
        : "memory");
}

#define TCG_LD_X32(r, addr) \
    asm volatile("tcgen05.ld.sync.aligned.32x32b.x32.b32 " \
        "{%0,%1,%2,%3,%4,%5,%6,%7,%8,%9,%10,%11,%12,%13,%14,%15," \
        "%16,%17,%18,%19,%20,%21,%22,%23,%24,%25,%26,%27,%28,%29,%30,%31}, [%32];" \
        : "=r"((r)[0]),"=r"((r)[1]),"=r"((r)[2]),"=r"((r)[3]),"=r"((r)[4]),"=r"((r)[5]),"=r"((r)[6]),"=r"((r)[7]), \
          "=r"((r)[8]),"=r"((r)[9]),"=r"((r)[10]),"=r"((r)[11]),"=r"((r)[12]),"=r"((r)[13]),"=r"((r)[14]),"=r"((r)[15]), \
          "=r"((r)[16]),"=r"((r)[17]),"=r"((r)[18]),"=r"((r)[19]),"=r"((r)[20]),"=r"((r)[21]),"=r"((r)[22]),"=r"((r)[23]), \
          "=r"((r)[24]),"=r"((r)[25]),"=r"((r)[26]),"=r"((r)[27]),"=r"((r)[28]),"=r"((r)[29]),"=r"((r)[30]),"=r"((r)[31]) \
        : "r"(addr))

#define TCG_ST_X32(addr, r) \
    asm volatile("tcgen05.st.sync.aligned.32x32b.x32.b32 [%0], " \
        "{%1,%2,%3,%4,%5,%6,%7,%8,%9,%10,%11,%12,%13,%14,%15,%16," \
        "%17,%18,%19,%20,%21,%22,%23,%24,%25,%26,%27,%28,%29,%30,%31,%32};" \
        :: "r"(addr), \
           "r"((r)[0]),"r"((r)[1]),"r"((r)[2]),"r"((r)[3]),"r"((r)[4]),"r"((r)[5]),"r"((r)[6]),"r"((r)[7]), \
           "r"((r)[8]),"r"((r)[9]),"r"((r)[10]),"r"((r)[11]),"r"((r)[12]),"r"((r)[13]),"r"((r)[14]),"r"((r)[15]), \
           "r"((r)[16]),"r"((r)[17]),"r"((r)[18]),"r"((r)[19]),"r"((r)[20]),"r"((r)[21]),"r"((r)[22]),"r"((r)[23]), \
           "r"((r)[24]),"r"((r)[25]),"r"((r)[26]),"r"((r)[27]),"r"((r)[28]),"r"((r)[29]),"r"((r)[30]),"r"((r)[31]) \
        : "memory")

static __device__ __forceinline__ uint64_t make_desc_sw128(uint32_t base) {
    const uint64_t BASE =
        (uint64_t(2)  << 61) | (uint64_t(1) << 46) | (uint64_t(64) << 32) | (uint64_t(1) << 16);
    return BASE | ((uint64_t)(base >> 4) & 0x3FFF);
}
__device__ __forceinline__ uint32_t sw128(uint32_t b) { return b ^ ((b >> 3) & 0x70); }

// tf32 hi part: truncate mantissa to 13 bits (tf32-representable); lo = x - hi
__device__ __forceinline__ float tf32_hi(float x) {
    return __uint_as_float(__float_as_uint(x) & 0xFFFFE000u);
}

// idesc: dtype=F32(1<<4) | atype=TF32(2<<7) | btype=TF32(2<<10) | (N/8)<<17 | (M/16)<<24
#define IDESC_S 0x8200910u  /* M=128, N=128 */
#define IDESC_O 0x8080910u  /* M=128, N=32  */
#define IDESC_G 0x8400910u  /* M=128, N=256 */
#endif // HAS_TCGEN05

// ---------------------------------------------------------------------------
// tcgen05 3xTF32 projection GEMM: C[128,256] per CTA = A @ W^T + b (+A2 resid)
//   Operands split x = hi + lo; D += Ah*Wh + Ah*Wl + Al*Wh  (near-fp32).
//   8 k-chunks of 32. Tiles: A_hi/A_lo 16KB each, W_hi/W_lo 32KB each.
//   TMEM D = 256 fp32 cols. Block 256 threads, 2 CTA/SM (194KB smem/SM).
// ---------------------------------------------------------------------------
#define G_AH_OFF 1024
#define G_AL_OFF (G_AH_OFF + 16384)
#define G_WH_OFF (G_AL_OFF + 16384)
#define G_WL_OFF (G_WH_OFF + 32768)
#define GEMM_SMEM (G_WL_OFF + 32768)

__global__ void __launch_bounds__(256, 2)
gemm_tc(const float* __restrict__ A, const float* __restrict__ A2,
        const float* __restrict__ W, const float* __restrict__ b,
        float* __restrict__ C) {
    int tid = threadIdx.x;
    size_t row0 = (size_t)blockIdx.x * 128;
#if HAS_TCGEN05
    extern __shared__ char smem[];
    uint32_t sb = smem_u32(smem);
    int wid = tid >> 5;

    if (wid == 0) TCG_ALLOC(sb, 256);
    if (tid == 0) MBAR_INIT(sb + 8, 1);
    __syncthreads();
    uint32_t tb;
    asm volatile("ld.shared.b32 %0, [%1];" : "=r"(tb) : "r"(sb));
    if (wid == 0) TCG_RELINQ();

    uint64_t adesc_h = make_desc_sw128(sb + G_AH_OFF);
    uint64_t adesc_l = make_desc_sw128(sb + G_AL_OFF);
    uint64_t wdesc_h = make_desc_sw128(sb + G_WH_OFF);
    uint64_t wdesc_l = make_desc_sw128(sb + G_WL_OFF);

    for (int kc = 0; kc < 8; kc++) {
        if (kc) {
            mbar_wait(sb + 8, (uint32_t)((kc - 1) & 1));  // prev MMA done before overwrite
            TCG_FENCE_AFTER();
        }
        // A tile: 128 rows x 32 floats (1024 float4), split hi/lo
#pragma unroll
        for (int i = 0; i < 4; i++) {
            int f = i * 256 + tid;
            int r = f >> 3, c4 = f & 7;
            float4 av = *(const float4*)(A + (row0 + r) * 256 + kc * 32 + c4 * 4);
            if (A2) {
                const float4 a2 = *(const float4*)(A2 + (row0 + r) * 256 + kc * 32 + c4 * 4);
                av.x += a2.x; av.y += a2.y; av.z += a2.z; av.w += a2.w;
            }
            float4 hv, lv;
            hv.x = tf32_hi(av.x); lv.x = av.x - hv.x;
            hv.y = tf32_hi(av.y); lv.y = av.y - hv.y;
            hv.z = tf32_hi(av.z); lv.z = av.z - hv.z;
            hv.w = tf32_hi(av.w); lv.w = av.w - hv.w;
            uint32_t off = sw128((uint32_t)(r * 128 + c4 * 16));
            *(float4*)(smem + G_AH_OFF + off) = hv;
            *(float4*)(smem + G_AL_OFF + off) = lv;
        }
        // W tile: 256 rows x 32 floats (2048 float4), split hi/lo
#pragma unroll
        for (int i = 0; i < 8; i++) {
            int f = i * 256 + tid;
            int r = f >> 3, c4 = f & 7;
            float4 wv = *(const float4*)(W + (size_t)r * 256 + kc * 32 + c4 * 4);
            float4 hv, lv;
            hv.x = tf32_hi(wv.x); lv.x = wv.x - hv.x;
            hv.y = tf32_hi(wv.y); lv.y = wv.y - hv.y;
            hv.z = tf32_hi(wv.z); lv.z = wv.z - hv.z;
            hv.w = tf32_hi(wv.w); lv.w = wv.w - hv.w;
            uint32_t off = sw128((uint32_t)(r * 128 + c4 * 16));
            *(float4*)(smem + G_WH_OFF + off) = hv;
            *(float4*)(smem + G_WL_OFF + off) = lv;
        }
        FENCE_ASYNC_SHARED();
        __syncthreads();

        if (wid == 0) {
            TCG_FENCE_AFTER();
            if (elect_one()) {
#pragma unroll
                for (int s = 0; s < 4; s++) {
                    bool first = (kc == 0) && (s == 0);
                    mma_tf32_ss(tb, adesc_h + s * 2, wdesc_h + s * 2, IDESC_G, !first);
                    mma_tf32_ss(tb, adesc_h + s * 2, wdesc_l + s * 2, IDESC_G, true);
                    mma_tf32_ss(tb, adesc_l + s * 2, wdesc_h + s * 2, IDESC_G, true);
                }
                TCG_COMMIT(sb + 8);
            }
        }
    }
    mbar_wait(sb + 8, 1u);  // chunk 7 committed -> parity 7&1
    TCG_FENCE_AFTER();

    // Epilogue: wg0 cols [0,128), wg1 cols [128,256); lane row = tid & 127
    int wg = tid >> 7;
    int row = (int)row0 + (tid & 127);
#pragma unroll
    for (int cc = 0; cc < 4; cc++) {
        int col0 = wg * 128 + cc * 32;
        uint32_t r[32];
        TCG_LD_X32(r, tb + col0);
        TCG_WAIT_LD();
        float4 v[8];
#pragma unroll
        for (int j = 0; j < 32; j++)
            (&v[j >> 2].x)[j & 3] = __uint_as_float(r[j]) + __ldg(b + col0 + j);
#pragma unroll
        for (int q4 = 0; q4 < 8; q4++)
            *(float4*)(C + (size_t)row * 256 + col0 + q4 * 4) = v[q4];
    }

    TCG_FENCE_BEFORE();
    __syncthreads();
    if (wid == 0) TCG_DEALLOC(tb, 256);
#else
    // Fallback (compile-only on generic pass; GB300 runs the sm_103a path)
    for (int idx = tid; idx < 128 * 256; idx += 256) {
        int r = idx >> 8, c = idx & 255;
        float acc = b[c];
        for (int k = 0; k < 256; k++) {
            float a = A[(row0 + r) * 256 + k];
            if (A2) a += A2[(row0 + r) * 256 + k];
            acc += a * W[(size_t)c * 256 + k];
        }
        C[(row0 + r) * 256 + c] = acc;
    }
#endif
}

// ---------------------------------------------------------------------------
// Attention kernel: tcgen05 tf32 path if available, SIMT flash fallback else.
//   grid (NP/128, HEADS, N_B), block 128, dynamic smem ATTN_SMEM
// ---------------------------------------------------------------------------
#define SMEM_K_OFF 1024
#define SMEM_V_OFF (1024 + 16384)
#define ATTN_SMEM  (1024 + 32768)
#define TM_Q 0
#define TM_O 32
#define TM_S 128
#define TM_COLS 256

__global__ void __launch_bounds__(128, 2)
attn_tc_kernel() {
    extern __shared__ char smem[];
    int tid = threadIdx.x;
    int qt = blockIdx.x, h = blockIdx.y, n = blockIdx.z;

#if HAS_TCGEN05
    uint32_t sb = smem_u32(smem);
    int wid = tid >> 5;

    if (wid == 0) TCG_ALLOC(sb, TM_COLS);
    if (tid == 0) { MBAR_INIT(sb + 8, 1); MBAR_INIT(sb + 16, 1); }
    __syncthreads();
    uint32_t tb;
    asm volatile("ld.shared.b32 %0, [%1];" : "=r"(tb) : "r"(sb));
    if (wid == 0) TCG_RELINQ();

    uint32_t woff = (uint32_t)wid << 21;

    // Stage Q (pre-scaled by 1/sqrt(DH)) into TMEM: row = tid, 32 tf32 cols
    {
        const float* Qp = d_Q + ((size_t)(n * NP + qt * 128 + tid)) * D + h * DH;
        uint32_t qr[32];
#pragma unroll
        for (int i = 0; i < 32; i++)
            qr[i] = __float_as_uint(Qp[i] * 0.17677669529663687f);
        TCG_ST_X32(tb + TM_Q + woff, qr);
        TCG_WAIT_ST();
    }
    TCG_FENCE_BEFORE();
    __syncthreads();

    const float* Kb = d_K + (size_t)n * HW * D + h * DH;
    const float* Vb = d_V + (size_t)n * HW * D + h * DH;
    uint64_t kdesc = make_desc_sw128(sb + SMEM_K_OFF);
    uint64_t vdesc = make_desc_sw128(sb + SMEM_V_OFF);
    float l = 0.f;

    for (int t = 0; t < 32; t++) {
        uint32_t par = (uint32_t)(t & 1);

        // K tile: SW128 K-major (row=key, 32 tf32 = 128B). V tile: transposed
        // blocked-atom layout (atom 8 dh-rows x 32 keys, atom_off = ar + ac*4).
#pragma unroll
        for (int i = 0; i < 8; i++) {
            int f = i * 128 + tid;
            int k = f >> 3;
            int c = (f & 7) * 4;
            const float4 kv = *(const float4*)(Kb + (size_t)(t * 128 + k) * D + c);
            *(float4*)(smem + SMEM_K_OFF + sw128((uint32_t)(k * 128 + c * 4))) = kv;
            const float4 vv = *(const float4*)(Vb + (size_t)(t * 128 + k) * D + c);
            int ac = k >> 5, ic = k & 31;
#pragma unroll
            for (int j = 0; j < 4; j++) {
                int dh = c + j;
                uint32_t vb = (uint32_t)(((dh >> 3) + ac * 4) * 1024 + (dh & 7) * 128 + ic * 4);
                *(float*)(smem + SMEM_V_OFF + sw128(vb)) = (&vv.x)[j];
            }
        }
        FENCE_ASYNC_SHARED();
        __syncthreads();

        // S = Q @ K^T  (M=128, N=128, K=32 -> 4 tf32 k-steps of K=8)
        if (wid == 0) {
            TCG_FENCE_AFTER();
            if (elect_one()) {
#pragma unroll
                for (int s = 0; s < 4; s++)
                    mma_tf32_ts(tb + TM_S, tb + TM_Q + s * 8, kdesc + s * 2, IDESC_S, s > 0);
                TCG_COMMIT(sb + 8);
            }
        }
        mbar_wait(sb + 8, par);
        TCG_FENCE_AFTER();

        // softmax without max-subtraction (scores bounded ~|10|): P = exp(S)
#pragma unroll
        for (int cc = 0; cc < 4; cc++) {
            uint32_t r[32];
            TCG_LD_X32(r, tb + TM_S + cc * 32);
            TCG_WAIT_LD();
#pragma unroll
            for (int j = 0; j < 32; j++) {
                float p = __expf(__uint_as_float(r[j]));
                l += p;
                r[j] = __float_as_uint(p);
            }
            TCG_ST_X32(tb + TM_S + cc * 32 + woff, r);
        }
        TCG_WAIT_ST();
        TCG_FENCE_BEFORE();
        __syncthreads();

        // O += P @ V  (M=128, N=32, K=128 -> 16 k-steps over V^T atoms)
        if (wid == 0) {
            TCG_FENCE_AFTER();
            if (elect_one()) {
#pragma unroll
                for (int s = 0; s < 16; s++)
                    mma_tf32_ts(tb + TM_O, tb + TM_S + s * 8,
                                vdesc + (uint64_t)((s >> 2) * 256 + (s & 3) * 2),
                                IDESC_O, (t > 0) || (s > 0));
                TCG_COMMIT(sb + 16);
            }
        }
        mbar_wait(sb + 16, par);
    }

    TCG_FENCE_AFTER();
    uint32_t o[32];
    TCG_LD_X32(o, tb + TM_O);
    TCG_WAIT_LD();
    float inv = 1.f / l;
    float* Op = d_AO + ((size_t)(n * NP + qt * 128 + tid)) * D + h * DH;
#pragma unroll
    for (int j = 0; j < 32; j++) Op[j] = __uint_as_float(o[j]) * inv;

    TCG_FENCE_BEFORE();
    __syncthreads();
    if (wid == 0) TCG_DEALLOC(tb, TM_COLS);

#else  // ---------------- SIMT fallback (known-good round-1 path) ----------
    float* Ks = (float*)smem;                 // [64][32]
    float* Vs = (float*)smem + 64 * 32;       // [64][32]
    int q = qt * 128 + tid;

    const float* Qp = d_Q + ((size_t)(n * NP + q)) * D + h * DH;
    float qr[32];
#pragma unroll
    for (int i = 0; i < 32; i++) qr[i] = Qp[i] * 0.17677669529663687f;

    float o[32];
#pragma unroll
    for (int i = 0; i < 32; i++) o[i] = 0.f;
    float m = -1e30f, l = 0.f;

    const float* Kb = d_K + (size_t)n * HW * D + h * DH;
    const float* Vb = d_V + (size_t)n * HW * D + h * DH;

    for (int k0 = 0; k0 < HW; k0 += 64) {
        __syncthreads();
        for (int i = tid; i < 512; i += 128) {
            int r = i >> 3, c = i & 7;
            ((float4*)(Ks + r * 32))[c] = *(const float4*)(Kb + (size_t)(k0 + r) * D + c * 4);
            ((float4*)(Vs + r * 32))[c] = *(const float4*)(Vb + (size_t)(k0 + r) * D + c * 4);
        }
        __syncthreads();

        float s[64];
#pragma unroll
        for (int k = 0; k < 64; k++) {
            float acc = 0.f;
            const float4* kr = (const float4*)(Ks + k * 32);
#pragma unroll
            for (int c = 0; c < 8; c++) {
                float4 kv = kr[c];
                acc += qr[c * 4 + 0] * kv.x;
                acc += qr[c * 4 + 1] * kv.y;
                acc += qr[c * 4 + 2] * kv.z;
                acc += qr[c * 4 + 3] * kv.w;
            }
            s[k] = acc;
        }
        float mt = m;
#pragma unroll
        for (int k = 0; k < 64; k++) mt = fmaxf(mt, s[k]);
        float scale = __expf(m - mt);
        m = mt;
        l *= scale;
#pragma unroll
        for (int i = 0; i < 32; i++) o[i] *= scale;
#pragma unroll
        for (int k = 0; k < 64; k++) {
            float p = __expf(s[k] - m);
            l += p;
            const float4* vr = (const float4*)(Vs + k * 32);
#pragma unroll
            for (int c = 0; c < 8; c++) {
                float4 vv = vr[c];
                o[c * 4 + 0] += p * vv.x;
                o[c * 4 + 1] += p * vv.y;
                o[c * 4 + 2] += p * vv.z;
                o[c * 4 + 3] += p * vv.w;
            }
        }
    }
    float inv = 1.f / l;
    float* Op = d_AO + ((size_t)(n * NP + q)) * D + h * DH;
#pragma unroll
    for (int i = 0; i < 32; i++) Op[i] = o[i] * inv;
#endif
}

// ---------------------------------------------------------------------------
extern "C" void kernel_launch(void* const* d_in, const int* in_sizes, int n_in,
                              void* d_out, int out_size) {
    const float* lf = (const float*)d_in[0];
    const float* gf = (const float*)d_in[1];
    const float* Wq = (const float*)d_in[2];
    const float* bq = (const float*)d_in[3];
    const float* Wk = (const float*)d_in[4];
    const float* bk = (const float*)d_in[5];
    const float* Wv = (const float*)d_in[6];
    const float* bv = (const float*)d_in[7];
    const float* Wo = (const float*)d_in[8];
    const float* bo = (const float*)d_in[9];
    float* out = (float*)d_out;

    float *lf_pe, *gf_pe, *Q, *K, *V, *AO;
    cudaGetSymbolAddress((void**)&lf_pe, d_lf_pe);
    cudaGetSymbolAddress((void**)&gf_pe, d_gf_pe);
    cudaGetSymbolAddress((void**)&Q, d_Q);
    cudaGetSymbolAddress((void**)&K, d_K);
    cudaGetSymbolAddress((void**)&V, d_V);
    cudaGetSymbolAddress((void**)&AO, d_AO);

    cudaFuncSetAttribute(gemm_tc, cudaFuncAttributeMaxDynamicSharedMemorySize, GEMM_SMEM);

    add_pe_local<<<(N_B * NP * D) / 256, 256>>>(lf);
    add_pe_global<<<dim3(HW / 32, D / 32, N_B), dim3(32, 8)>>>(gf);

    gemm_tc<<<(N_B * NP) / 128, 256, GEMM_SMEM>>>(lf_pe, nullptr, Wq, bq, Q);
    gemm_tc<<<(N_B * HW) / 128, 256, GEMM_SMEM>>>(gf_pe, nullptr, Wk, bk, K);
    gemm_tc<<<(N_B * HW) / 128, 256, GEMM_SMEM>>>(gf_pe, nullptr, Wv, bv, V);

    attn_tc_kernel<<<dim3(NP / 128, HEADS, N_B), 128, ATTN_SMEM>>>();

    gemm_tc<<<(N_B * NP) / 128, 256, GEMM_SMEM>>>(lf_pe, AO, Wo, bo, out);
}

// round 14
// speedup vs baseline: 5.0454x; 1.1129x over previous
#include <cuda_runtime.h>
#include <math.h>
#include <stdint.h>

#define N_B   4
#define NP    1024
#define D     256
#define HW    4096
#define HEADS 8
#define DH    32

// Scratch (device globals: no allocation allowed in kernel_launch)
__device__ float d_lf_pe[N_B * NP * D];   //  4 MB
__device__ float d_gf_pe[N_B * HW * D];   // 16 MB
__device__ float d_Q[N_B * NP * D];       //  4 MB
__device__ float d_K[N_B * HW * D];       // 16 MB
__device__ float d_V[N_B * HW * D];       // 16 MB
__device__ float d_AO[N_B * NP * D];      //  4 MB

// tcgen05 only legal when compiling an arch-specific ('a') target.
#if defined(__CUDA_ARCH_FEAT_SM103_ALL) || defined(__CUDA_ARCH_FEAT_SM100_ALL) || defined(__CUDA_ARCH_FEAT_SM101_ALL)
#define HAS_TCGEN05 1
#else
#define HAS_TCGEN05 0
#endif

// ---------------------------------------------------------------------------
// Positional encodings (fast-math MUFU intrinsics; abs err ~5e-7 << 1e-3)
// ---------------------------------------------------------------------------
__device__ __forceinline__ float pe_val(int p, int dd, int g) {
    int i = dd >> 1;
    float div = __expf((float)(2 * i) * (-9.210340371976184f / 256.0f));
    float coord = (dd & 1) ? (float)(p / g) : (float)(p % g);
    coord *= 1.0f / (float)(g - 1);
    float a = coord * div;
    return (dd & 1) ? __cosf(a) : __sinf(a);
}

__global__ void add_pe_local(const float* __restrict__ lf) {
    int idx = blockIdx.x * blockDim.x + threadIdx.x;
    if (idx >= N_B * NP * D) return;
    int dd = idx & (D - 1);
    int p  = (idx / D) & (NP - 1);
    d_lf_pe[idx] = lf[idx] + pe_val(p, dd, 32);
}

__global__ void add_pe_global(const float* __restrict__ gf) {
    __shared__ float tile[32][33];
    int p0 = blockIdx.x * 32, d0 = blockIdx.y * 32, n = blockIdx.z;
    int tx = threadIdx.x, ty = threadIdx.y;
#pragma unroll
    for (int i = 0; i < 4; i++) {
        int dd = d0 + ty + i * 8;
        tile[ty + i * 8][tx] = gf[((size_t)n * D + dd) * HW + p0 + tx];
    }
    __syncthreads();
#pragma unroll
    for (int i = 0; i < 4; i++) {
        int p  = p0 + ty + i * 8;
        int dd = d0 + tx;
        d_gf_pe[((size_t)n * HW + p) * D + dd] = tile[tx][ty + i * 8] + pe_val(p, dd, 64);
    }
}

// ---------------------------------------------------------------------------
// PTX helpers (guarded)
// ---------------------------------------------------------------------------
#if HAS_TCGEN05
__device__ __forceinline__ uint32_t smem_u32(const void* p) {
    uint32_t a;
    asm("{ .reg .u64 t; cvta.to.shared.u64 t, %1; cvt.u32.u64 %0, t; }" : "=r"(a) : "l"(p));
    return a;
}
__device__ __forceinline__ uint32_t elect_one() {
    uint32_t p;
    asm volatile("{\n\t.reg .pred p;\n\telect.sync _|p, 0xFFFFFFFF;\n\tselp.b32 %0, 1, 0, p;\n\t}" : "=r"(p));
    return p;
}

#define TCG_ALLOC(sm, n)  asm volatile("tcgen05.alloc.cta_group::1.sync.aligned.shared::cta.b32 [%0], %1;" :: "r"(sm), "r"(n) : "memory")
#define TCG_DEALLOC(t, n) asm volatile("tcgen05.dealloc.cta_group::1.sync.aligned.b32 %0, %1;" :: "r"(t), "r"(n))
#define TCG_RELINQ()      asm volatile("tcgen05.relinquish_alloc_permit.cta_group::1.sync.aligned;")
#define TCG_COMMIT(mbar)  asm volatile("tcgen05.commit.cta_group::1.mbarrier::arrive::one.shared::cluster.b64 [%0];" :: "r"(mbar) : "memory")
#define TCG_WAIT_LD()     asm volatile("tcgen05.wait::ld.sync.aligned;" ::: "memory")
#define TCG_WAIT_ST()     asm volatile("tcgen05.wait::st.sync.aligned;" ::: "memory")
#define TCG_FENCE_BEFORE() asm volatile("tcgen05.fence::before_thread_sync;" ::: "memory")
#define TCG_FENCE_AFTER()  asm volatile("tcgen05.fence::after_thread_sync;" ::: "memory")
#define FENCE_ASYNC_SHARED() asm volatile("fence.proxy.async.shared::cta;" ::: "memory")
#define MBAR_INIT(m, c)   asm volatile("mbarrier.init.shared.b64 [%0], %1;" :: "r"(m), "r"(c) : "memory")

__device__ __forceinline__ void mbar_wait(uint32_t mbar, uint32_t parity) {
    asm volatile(
        "{\n\t.reg .pred P;\n\t"
        "W_%=:\n\t"
        "mbarrier.try_wait.parity.acquire.cta.shared::cta.b64 P, [%0], %1, 0x989680;\n\t"
        "@!P bra W_%=;\n\t}"
        :: "r"(mbar), "r"(parity) : "memory");
}

// tf32 MMA, TS form (A in TMEM)
__device__ __forceinline__ void mma_tf32_ts(uint32_t d_tmem, uint32_t a_tmem,
                                            uint64_t b_desc, uint32_t idesc, bool acc) {
    uint32_t en = acc ? 1u : 0u;
    uint32_t z = 0;
    asm volatile(
        "{\n\t.reg .pred p;\n\t"
        "setp.ne.u32 p, %5, 0;\n\t"
        "tcgen05.mma.cta_group::1.kind::tf32 [%0], [%1], %2, %3, {%4, %4, %4, %4}, p;\n\t}"
        :: "r"(d_tmem), "r"(a_tmem), "l"(b_desc), "r"(idesc), "r"(z), "r"(en)
        : "memory");
}

// tf32 MMA, SS form (A via smem descriptor)
__device__ __forceinline__ void mma_tf32_ss(uint32_t d_tmem, uint64_t a_desc,
                                            uint64_t b_desc, uint32_t idesc, bool acc) {
    uint32_t en = acc ? 1u : 0u;
    uint32_t z = 0;
    asm volatile(
        "{\n\t.reg .pred p;\n\t"
        "setp.ne.u32 p, %5, 0;\n\t"
        "tcgen05.mma.cta_group::1.kind::tf32 [%0], %1, %2, %3, {%4, %4, %4, %4}, p;\n\t}"
        :: "r"(d_tmem), "l"(a_desc), "l"(b_desc), "r"(idesc), "r"(z), "r"(en)
        : "memory");
}

#define TCG_LD_X32(r, addr) \
    asm volatile("tcgen05.ld.sync.aligned.32x32b.x32.b32 " \
        "{%0,%1,%2,%3,%4,%5,%6,%7,%8,%9,%10,%11,%12,%13,%14,%15," \
        "%16,%17,%18,%19,%20,%21,%22,%23,%24,%25,%26,%27,%28,%29,%30,%31}, [%32];" \
        : "=r"((r)[0]),"=r"((r)[1]),"=r"((r)[2]),"=r"((r)[3]),"=r"((r)[4]),"=r"((r)[5]),"=r"((r)[6]),"=r"((r)[7]), \
          "=r"((r)[8]),"=r"((r)[9]),"=r"((r)[10]),"=r"((r)[11]),"=r"((r)[12]),"=r"((r)[13]),"=r"((r)[14]),"=r"((r)[15]), \
          "=r"((r)[16]),"=r"((r)[17]),"=r"((r)[18]),"=r"((r)[19]),"=r"((r)[20]),"=r"((r)[21]),"=r"((r)[22]),"=r"((r)[23]), \
          "=r"((r)[24]),"=r"((r)[25]),"=r"((r)[26]),"=r"((r)[27]),"=r"((r)[28]),"=r"((r)[29]),"=r"((r)[30]),"=r"((r)[31]) \
        : "r"(addr))

#define TCG_ST_X32(addr, r) \
    asm volatile("tcgen05.st.sync.aligned.32x32b.x32.b32 [%0], " \
        "{%1,%2,%3,%4,%5,%6,%7,%8,%9,%10,%11,%12,%13,%14,%15,%16," \
        "%17,%18,%19,%20,%21,%22,%23,%24,%25,%26,%27,%28,%29,%30,%31,%32};" \
        :: "r"(addr), \
           "r"((r)[0]),"r"((r)[1]),"r"((r)[2]),"r"((r)[3]),"r"((r)[4]),"r"((r)[5]),"r"((r)[6]),"r"((r)[7]), \
           "r"((r)[8]),"r"((r)[9]),"r"((r)[10]),"r"((r)[11]),"r"((r)[12]),"r"((r)[13]),"r"((r)[14]),"r"((r)[15]), \
           "r"((r)[16]),"r"((r)[17]),"r"((r)[18]),"r"((r)[19]),"r"((r)[20]),"r"((r)[21]),"r"((r)[22]),"r"((r)[23]), \
           "r"((r)[24]),"r"((r)[25]),"r"((r)[26]),"r"((r)[27]),"r"((r)[28]),"r"((r)[29]),"r"((r)[30]),"r"((r)[31]) \
        : "memory")

static __device__ __forceinline__ uint64_t make_desc_sw128(uint32_t base) {
    const uint64_t BASE =
        (uint64_t(2)  << 61) | (uint64_t(1) << 46) | (uint64_t(64) << 32) | (uint64_t(1) << 16);
    return BASE | ((uint64_t)(base >> 4) & 0x3FFF);
}
__device__ __forceinline__ uint32_t sw128(uint32_t b) { return b ^ ((b >> 3) & 0x70); }

// tf32 hi part: truncate mantissa to 13 bits; lo = x - hi
__device__ __forceinline__ float tf32_hi(float x) {
    return __uint_as_float(__float_as_uint(x) & 0xFFFFE000u);
}

// idesc: dtype=F32(1<<4) | atype=TF32(2<<7) | btype=TF32(2<<10) | (N/8)<<17 | (M/16)<<24
#define IDESC_S 0x8200910u  /* M=128, N=128 */
#define IDESC_O 0x8080910u  /* M=128, N=32  */
#define IDESC_G 0x8400910u  /* M=128, N=256 */
#endif // HAS_TCGEN05

// ---------------------------------------------------------------------------
// tcgen05 3xTF32 projection GEMM, double-buffered with per-buffer mbarriers
// (<=1 outstanding phase per mbarrier -> parity-exact, no aliasing deadlock).
//   C[128,256] per CTA = (A (+A2)) @ W^T + b. 8 k-chunks of 32.
//   mbar[b] at sb+8+8b collects commits of chunks kc == b (mod 2).
// ---------------------------------------------------------------------------
#define GB_AH 0
#define GB_AL 16384
#define GB_WH 32768
#define GB_WL 65536
#define GB_SIZE 98304
#define G_BUF0 1024
#define GEMM_SMEM (G_BUF0 + 2 * GB_SIZE)

#if HAS_TCGEN05
__device__ __forceinline__ void g_ldg(const float* __restrict__ A,
                                      const float* __restrict__ A2,
                                      const float* __restrict__ W,
                                      size_t row0, int kc, int tid,
                                      float4* ar, float4* wr) {
#pragma unroll
    for (int i = 0; i < 4; i++) {
        int f = i * 256 + tid;
        int r = f >> 3, c4 = f & 7;
        float4 av = *(const float4*)(A + (row0 + r) * 256 + kc * 32 + c4 * 4);
        if (A2) {
            const float4 a2 = *(const float4*)(A2 + (row0 + r) * 256 + kc * 32 + c4 * 4);
            av.x += a2.x; av.y += a2.y; av.z += a2.z; av.w += a2.w;
        }
        ar[i] = av;
    }
#pragma unroll
    for (int i = 0; i < 8; i++) {
        int f = i * 256 + tid;
        int r = f >> 3, c4 = f & 7;
        wr[i] = *(const float4*)(W + (size_t)r * 256 + kc * 32 + c4 * 4);
    }
}

__device__ __forceinline__ void g_sts(char* smem, uint32_t bufoff, int tid,
                                      const float4* ar, const float4* wr) {
#pragma unroll
    for (int i = 0; i < 4; i++) {
        int f = i * 256 + tid;
        int r = f >> 3, c4 = f & 7;
        float4 av = ar[i], hv, lv;
        hv.x = tf32_hi(av.x); lv.x = av.x - hv.x;
        hv.y = tf32_hi(av.y); lv.y = av.y - hv.y;
        hv.z = tf32_hi(av.z); lv.z = av.z - hv.z;
        hv.w = tf32_hi(av.w); lv.w = av.w - hv.w;
        uint32_t off = sw128((uint32_t)(r * 128 + c4 * 16));
        *(float4*)(smem + bufoff + GB_AH + off) = hv;
        *(float4*)(smem + bufoff + GB_AL + off) = lv;
    }
#pragma unroll
    for (int i = 0; i < 8; i++) {
        int f = i * 256 + tid;
        int r = f >> 3, c4 = f & 7;
        float4 wv = wr[i], hv, lv;
        hv.x = tf32_hi(wv.x); lv.x = wv.x - hv.x;
        hv.y = tf32_hi(wv.y); lv.y = wv.y - hv.y;
        hv.z = tf32_hi(wv.z); lv.z = wv.z - hv.z;
        hv.w = tf32_hi(wv.w); lv.w = wv.w - hv.w;
        uint32_t off = sw128((uint32_t)(r * 128 + c4 * 16));
        *(float4*)(smem + bufoff + GB_WH + off) = hv;
        *(float4*)(smem + bufoff + GB_WL + off) = lv;
    }
}
#endif

__global__ void __launch_bounds__(256, 1)
gemm_tc(const float* __restrict__ A, const float* __restrict__ A2,
        const float* __restrict__ W, const float* __restrict__ b,
        float* __restrict__ C) {
    int tid = threadIdx.x;
    size_t row0 = (size_t)blockIdx.x * 128;
#if HAS_TCGEN05
    extern __shared__ char smem[];
    uint32_t sb = smem_u32(smem);
    int wid = tid >> 5;

    if (wid == 0) TCG_ALLOC(sb, 256);
    if (tid == 0) { MBAR_INIT(sb + 8, 1); MBAR_INIT(sb + 16, 1); }
    __syncthreads();
    uint32_t tb;
    asm volatile("ld.shared.b32 %0, [%1];" : "=r"(tb) : "r"(sb));
    if (wid == 0) TCG_RELINQ();

    float4 ar[4], wr[8];

    // Prologue: chunk 0 into buffer 0
    g_ldg(A, A2, W, row0, 0, tid, ar, wr);
    g_sts(smem, G_BUF0, tid, ar, wr);
    FENCE_ASYNC_SHARED();
    __syncthreads();

    for (int kc = 0; kc < 8; kc++) {
        uint32_t bufoff = G_BUF0 + (uint32_t)(kc & 1) * GB_SIZE;
        uint64_t ah = make_desc_sw128(sb + bufoff + GB_AH);
        uint64_t al = make_desc_sw128(sb + bufoff + GB_AL);
        uint64_t wh = make_desc_sw128(sb + bufoff + GB_WH);
        uint64_t wl = make_desc_sw128(sb + bufoff + GB_WL);

        // MMA chunk kc from buffer kc&1, commit to mbar[kc&1]
        if (wid == 0) {
            TCG_FENCE_AFTER();
            if (elect_one()) {
#pragma unroll
                for (int s = 0; s < 4; s++) {
                    bool first = (kc == 0) && (s == 0);
                    mma_tf32_ss(tb, ah + s * 2, wh + s * 2, IDESC_G, !first);
                    mma_tf32_ss(tb, ah + s * 2, wl + s * 2, IDESC_G, true);
                    mma_tf32_ss(tb, al + s * 2, wh + s * 2, IDESC_G, true);
                }
                TCG_COMMIT(sb + 8 + 8 * (uint32_t)(kc & 1));
            }
        }

        if (kc < 7) {
            // Load next chunk while MMA kc runs
            g_ldg(A, A2, W, row0, kc + 1, tid, ar, wr);
            if (kc >= 1) {
                // Buffer (kc+1)&1 was read by MMA kc-1; its mbar is
                // mbar[(kc-1)&1] and the waited phase ((kc-1)>>1) is the
                // LAST phase issued on that mbar -> exact parity wait.
                mbar_wait(sb + 8 + 8 * (uint32_t)((kc + 1) & 1),
                          (uint32_t)(((kc - 1) >> 1) & 1));
                TCG_FENCE_AFTER();
            }
            g_sts(smem, G_BUF0 + (uint32_t)((kc + 1) & 1) * GB_SIZE, tid, ar, wr);
            FENCE_ASYNC_SHARED();
            __syncthreads();
        }
    }
    // Final: mbar0 phase 3 (kc=6), mbar1 phase 3 (kc=7) -> both parity 1
    mbar_wait(sb + 8, 1u);
    mbar_wait(sb + 16, 1u);
    TCG_FENCE_AFTER();

    // Epilogue: wg0 cols [0,128), wg1 cols [128,256)
    int wg = tid >> 7;
    int row = (int)row0 + (tid & 127);
#pragma unroll
    for (int cc = 0; cc < 4; cc++) {
        int col0 = wg * 128 + cc * 32;
        uint32_t r[32];
        TCG_LD_X32(r, tb + col0);
        TCG_WAIT_LD();
        float4 v[8];
#pragma unroll
        for (int j = 0; j < 32; j++)
            (&v[j >> 2].x)[j & 3] = __uint_as_float(r[j]) + __ldg(b + col0 + j);
#pragma unroll
        for (int q4 = 0; q4 < 8; q4++)
            *(float4*)(C + (size_t)row * 256 + col0 + q4 * 4) = v[q4];
    }

    TCG_FENCE_BEFORE();
    __syncthreads();
    if (wid == 0) TCG_DEALLOC(tb, 256);
#else
    // Fallback (compile-only on generic pass)
    for (int idx = tid; idx < 128 * 256; idx += 256) {
        int r = idx >> 8, c = idx & 255;
        float acc = b[c];
        for (int k = 0; k < 256; k++) {
            float a = A[(row0 + r) * 256 + k];
            if (A2) a += A2[(row0 + r) * 256 + k];
            acc += a * W[(size_t)c * 256 + k];
        }
        C[(row0 + r) * 256 + c] = acc;
    }
#endif
}

// ---------------------------------------------------------------------------
// tcgen05 tf32 flash attention (R10-proven version, unchanged).
//   grid (NP/128, HEADS, N_B), block 128, dynamic smem ATTN_SMEM
// ---------------------------------------------------------------------------
#define SMEM_K_OFF 1024
#define SMEM_V_OFF (1024 + 16384)
#define ATTN_SMEM  (1024 + 32768)
#define TM_Q 0
#define TM_O 32
#define TM_S 128
#define TM_COLS 256

__global__ void __launch_bounds__(128, 2)
attn_tc_kernel() {
    extern __shared__ char smem[];
    int tid = threadIdx.x;
    int qt = blockIdx.x, h = blockIdx.y, n = blockIdx.z;

#if HAS_TCGEN05
    uint32_t sb = smem_u32(smem);
    int wid = tid >> 5;

    if (wid == 0) TCG_ALLOC(sb, TM_COLS);
    if (tid == 0) { MBAR_INIT(sb + 8, 1); MBAR_INIT(sb + 16, 1); }
    __syncthreads();
    uint32_t tb;
    asm volatile("ld.shared.b32 %0, [%1];" : "=r"(tb) : "r"(sb));
    if (wid == 0) TCG_RELINQ();

    uint32_t woff = (uint32_t)wid << 21;

    // Stage Q (pre-scaled by 1/sqrt(DH)) into TMEM: row = tid, 32 tf32 cols
    {
        const float* Qp = d_Q + ((size_t)(n * NP + qt * 128 + tid)) * D + h * DH;
        uint32_t qr[32];
#pragma unroll
        for (int i = 0; i < 32; i++)
            qr[i] = __float_as_uint(Qp[i] * 0.17677669529663687f);
        TCG_ST_X32(tb + TM_Q + woff, qr);
        TCG_WAIT_ST();
    }
    TCG_FENCE_BEFORE();
    __syncthreads();

    const float* Kb = d_K + (size_t)n * HW * D + h * DH;
    const float* Vb = d_V + (size_t)n * HW * D + h * DH;
    uint64_t kdesc = make_desc_sw128(sb + SMEM_K_OFF);
    uint64_t vdesc = make_desc_sw128(sb + SMEM_V_OFF);
    float l = 0.f;

    for (int t = 0; t < 32; t++) {
        uint32_t par = (uint32_t)(t & 1);

        // K tile: SW128 K-major (row=key, 32 tf32 = 128B). V tile: transposed
        // blocked-atom layout (atom 8 dh-rows x 32 keys, atom_off = ar + ac*4).
#pragma unroll
        for (int i = 0; i < 8; i++) {
            int f = i * 128 + tid;
            int k = f >> 3;
            int c = (f & 7) * 4;
            const float4 kv = *(const float4*)(Kb + (size_t)(t * 128 + k) * D + c);
            *(float4*)(smem + SMEM_K_OFF + sw128((uint32_t)(k * 128 + c * 4))) = kv;
            const float4 vv = *(const float4*)(Vb + (size_t)(t * 128 + k) * D + c);
            int ac = k >> 5, ic = k & 31;
#pragma unroll
            for (int j = 0; j < 4; j++) {
                int dh = c + j;
                uint32_t vb = (uint32_t)(((dh >> 3) + ac * 4) * 1024 + (dh & 7) * 128 + ic * 4);
                *(float*)(smem + SMEM_V_OFF + sw128(vb)) = (&vv.x)[j];
            }
        }
        FENCE_ASYNC_SHARED();
        __syncthreads();

        // S = Q @ K^T  (M=128, N=128, K=32 -> 4 tf32 k-steps of K=8)
        if (wid == 0) {
            TCG_FENCE_AFTER();
            if (elect_one()) {
#pragma unroll
                for (int s = 0; s < 4; s++)
                    mma_tf32_ts(tb + TM_S, tb + TM_Q + s * 8, kdesc + s * 2, IDESC_S, s > 0);
                TCG_COMMIT(sb + 8);
            }
        }
        mbar_wait(sb + 8, par);
        TCG_FENCE_AFTER();

        // softmax without max-subtraction (scores bounded ~|10|): P = exp(S)
#pragma unroll
        for (int cc = 0; cc < 4; cc++) {
            uint32_t r[32];
            TCG_LD_X32(r, tb + TM_S + cc * 32);
            TCG_WAIT_LD();
#pragma unroll
            for (int j = 0; j < 32; j++) {
                float p = __expf(__uint_as_float(r[j]));
                l += p;
                r[j] = __float_as_uint(p);
            }
            TCG_ST_X32(tb + TM_S + cc * 32 + woff, r);
        }
        TCG_WAIT_ST();
        TCG_FENCE_BEFORE();
        __syncthreads();

        // O += P @ V  (M=128, N=32, K=128 -> 16 k-steps over V^T atoms)
        if (wid == 0) {
            TCG_FENCE_AFTER();
            if (elect_one()) {
#pragma unroll
                for (int s = 0; s < 16; s++)
                    mma_tf32_ts(tb + TM_O, tb + TM_S + s * 8,
                                vdesc + (uint64_t)((s >> 2) * 256 + (s & 3) * 2),
                                IDESC_O, (t > 0) || (s > 0));
                TCG_COMMIT(sb + 16);
            }
        }
        mbar_wait(sb + 16, par);
    }

    TCG_FENCE_AFTER();
    uint32_t o[32];
    TCG_LD_X32(o, tb + TM_O);
    TCG_WAIT_LD();
    float inv = 1.f / l;
    float* Op = d_AO + ((size_t)(n * NP + qt * 128 + tid)) * D + h * DH;
#pragma unroll
    for (int j = 0; j < 32; j++) Op[j] = __uint_as_float(o[j]) * inv;

    TCG_FENCE_BEFORE();
    __syncthreads();
    if (wid == 0) TCG_DEALLOC(tb, TM_COLS);

#else  // ---------------- SIMT fallback (compile-only on generic pass) -----
    float* Ks = (float*)smem;
    float* Vs = (float*)smem + 64 * 32;
    int q = qt * 128 + tid;

    const float* Qp = d_Q + ((size_t)(n * NP + q)) * D + h * DH;
    float qr[32];
#pragma unroll
    for (int i = 0; i < 32; i++) qr[i] = Qp[i] * 0.17677669529663687f;

    float o[32];
#pragma unroll
    for (int i = 0; i < 32; i++) o[i] = 0.f;
    float m = -1e30f, l = 0.f;

    const float* Kb = d_K + (size_t)n * HW * D + h * DH;
    const float* Vb = d_V + (size_t)n * HW * D + h * DH;

    for (int k0 = 0; k0 < HW; k0 += 64) {
        __syncthreads();
        for (int i = tid; i < 512; i += 128) {
            int r = i >> 3, c = i & 7;
            ((float4*)(Ks + r * 32))[c] = *(const float4*)(Kb + (size_t)(k0 + r) * D + c * 4);
            ((float4*)(Vs + r * 32))[c] = *(const float4*)(Vb + (size_t)(k0 + r) * D + c * 4);
        }
        __syncthreads();

        float s[64];
#pragma unroll
        for (int k = 0; k < 64; k++) {
            float acc = 0.f;
            const float4* kr = (const float4*)(Ks + k * 32);
#pragma unroll
            for (int c = 0; c < 8; c++) {
                float4 kv = kr[c];
                acc += qr[c*4+0]*kv.x + qr[c*4+1]*kv.y + qr[c*4+2]*kv.z + qr[c*4+3]*kv.w;
            }
            s[k] = acc;
        }
        float mt = m;
#pragma unroll
        for (int k = 0; k < 64; k++) mt = fmaxf(mt, s[k]);
        float scale = __expf(m - mt);
        m = mt; l *= scale;
#pragma unroll
        for (int i = 0; i < 32; i++) o[i] *= scale;
#pragma unroll
        for (int k = 0; k < 64; k++) {
            float p = __expf(s[k] - m);
            l += p;
            const float4* vr = (const float4*)(Vs + k * 32);
#pragma unroll
            for (int c = 0; c < 8; c++) {
                float4 vv = vr[c];
                o[c*4+0] += p*vv.x; o[c*4+1] += p*vv.y; o[c*4+2] += p*vv.z; o[c*4+3] += p*vv.w;
            }
        }
    }
    float inv = 1.f / l;
    float* Op = d_AO + ((size_t)(n * NP + q)) * D + h * DH;
#pragma unroll
    for (int i = 0; i < 32; i++) Op[i] = o[i] * inv;
#endif
}

// ---------------------------------------------------------------------------
extern "C" void kernel_launch(void* const* d_in, const int* in_sizes, int n_in,
                              void* d_out, int out_size) {
    const float* lf = (const float*)d_in[0];
    const float* gf = (const float*)d_in[1];
    const float* Wq = (const float*)d_in[2];
    const float* bq = (const float*)d_in[3];
    const float* Wk = (const float*)d_in[4];
    const float* bk = (const float*)d_in[5];
    const float* Wv = (const float*)d_in[6];
    const float* bv = (const float*)d_in[7];
    const float* Wo = (const float*)d_in[8];
    const float* bo = (const float*)d_in[9];
    float* out = (float*)d_out;

    float *lf_pe, *gf_pe, *Q, *K, *V, *AO;
    cudaGetSymbolAddress((void**)&lf_pe, d_lf_pe);
    cudaGetSymbolAddress((void**)&gf_pe, d_gf_pe);
    cudaGetSymbolAddress((void**)&Q, d_Q);
    cudaGetSymbolAddress((void**)&K, d_K);
    cudaGetSymbolAddress((void**)&V, d_V);
    cudaGetSymbolAddress((void**)&AO, d_AO);

    cudaFuncSetAttribute(gemm_tc, cudaFuncAttributeMaxDynamicSharedMemorySize, GEMM_SMEM);

    add_pe_local<<<(N_B * NP * D) / 256, 256>>>(lf);
    add_pe_global<<<dim3(HW / 32, D / 32, N_B), dim3(32, 8)>>>(gf);

    gemm_tc<<<(N_B * NP) / 128, 256, GEMM_SMEM>>>(lf_pe, nullptr, Wq, bq, Q);
    gemm_tc<<<(N_B * HW) / 128, 256, GEMM_SMEM>>>(gf_pe, nullptr, Wk, bk, K);
    gemm_tc<<<(N_B * HW) / 128, 256, GEMM_SMEM>>>(gf_pe, nullptr, Wv, bv, V);

    attn_tc_kernel<<<dim3(NP / 128, HEADS, N_B), 128, ATTN_SMEM>>>();

    gemm_tc<<<(N_B * NP) / 128, 256, GEMM_SMEM>>>(lf_pe, AO, Wo, bo, out);
}